// round 2
// baseline (speedup 1.0000x reference)
#include <cuda_runtime.h>

// CompressedInteractionNetwork: 3-layer CIN, B=2048, H=39, D=16, S=128.
// One warp per batch element; packed f32x2 FMA over the d-dimension.

#define NB 4                 // batches per block (one warp each)
#define THREADS (NB * 32)
#define H0 39
#define DPAIRS 8             // D=16 -> 8 f32x2 pairs

__device__ __forceinline__ unsigned long long fma2(unsigned long long a,
                                                   unsigned long long b,
                                                   unsigned long long c) {
    unsigned long long d;
    asm("fma.rn.f32x2 %0, %1, %2, %3;" : "=l"(d) : "l"(a), "l"(b), "l"(c));
    return d;
}
__device__ __forceinline__ unsigned long long mul2(unsigned long long a,
                                                   unsigned long long b) {
    unsigned long long d;
    asm("mul.rn.f32x2 %0, %1, %2;" : "=l"(d) : "l"(a), "l"(b));
    return d;
}
__device__ __forceinline__ unsigned long long pack2(float lo, float hi) {
    unsigned long long d;
    asm("mov.b64 %0, {%1, %2};" : "=l"(d) : "f"(lo), "f"(hi));
    return d;
}
__device__ __forceinline__ void unpack2(unsigned long long v, float &lo, float &hi) {
    asm("mov.b64 {%0, %1}, %2;" : "=f"(lo), "=f"(hi) : "l"(v));
}

// One CIN layer for one batch element, executed by one warp.
//   z[s][d] = sum_{h<39,k<K} x0[h][d] * xk[k][d] * W[h*K*128 + k*128 + s]
// lane owns s in {4*lane .. 4*lane+3}, all 16 d as 8 f32x2 accumulators.
template <int K, int LAYER>
__device__ __forceinline__ void do_layer(const float* __restrict__ W,
                                         const float* __restrict__ bias,
                                         const unsigned long long* __restrict__ sx0,
                                         unsigned long long* __restrict__ sxk,
                                         int lane,
                                         float* __restrict__ outp) {
    unsigned long long acc[4][DPAIRS];
#pragma unroll
    for (int si = 0; si < 4; ++si)
#pragma unroll
        for (int j = 0; j < DPAIRS; ++j) acc[si][j] = 0ull;

    const float* Wl = W + lane * 4;

#pragma unroll 1
    for (int h = 0; h < H0; ++h) {
        unsigned long long a8[DPAIRS];
        const ulonglong2* arow = (const ulonglong2*)(sx0 + h * DPAIRS);
#pragma unroll
        for (int jj = 0; jj < 4; ++jj) {
            ulonglong2 t = arow[jj];
            a8[2 * jj] = t.x;
            a8[2 * jj + 1] = t.y;
        }
        const float* Whk = Wl + h * K * 128;
        float4 w = *(const float4*)(Whk);   // prefetch k=0
#pragma unroll 2
        for (int k = 0; k < K; ++k) {
            float4 wc = w;
            if (k + 1 < K) w = *(const float4*)(Whk + (k + 1) * 128);  // prefetch next

            unsigned long long c8[DPAIRS];
            const ulonglong2* crow = (const ulonglong2*)(sxk + k * DPAIRS);
#pragma unroll
            for (int jj = 0; jj < 4; ++jj) {
                ulonglong2 t = crow[jj];
                c8[2 * jj] = t.x;
                c8[2 * jj + 1] = t.y;
            }
            unsigned long long p[DPAIRS];
#pragma unroll
            for (int j = 0; j < DPAIRS; ++j) p[j] = mul2(a8[j], c8[j]);

            unsigned long long w0p = pack2(wc.x, wc.x);
            unsigned long long w1p = pack2(wc.y, wc.y);
            unsigned long long w2p = pack2(wc.z, wc.z);
            unsigned long long w3p = pack2(wc.w, wc.w);
#pragma unroll
            for (int j = 0; j < DPAIRS; ++j) {
                acc[0][j] = fma2(p[j], w0p, acc[0][j]);
                acc[1][j] = fma2(p[j], w1p, acc[1][j]);
                acc[2][j] = fma2(p[j], w2p, acc[2][j]);
                acc[3][j] = fma2(p[j], w3p, acc[3][j]);
            }
        }
    }

    __syncwarp();  // all lanes done reading sxk before we overwrite it

#pragma unroll
    for (int si = 0; si < 4; ++si) {
        int s = lane * 4 + si;
        float bv = bias[s];
        if (LAYER < 2 && s < 64) {
            // lower half -> new xk (relu(z + b)) into shared
            unsigned long long row[DPAIRS];
#pragma unroll
            for (int j = 0; j < DPAIRS; ++j) {
                float lo, hi;
                unpack2(acc[si][j], lo, hi);
                lo = fmaxf(lo + bv, 0.f);
                hi = fmaxf(hi + bv, 0.f);
                row[j] = pack2(lo, hi);
            }
            ulonglong2* dst = (ulonglong2*)(sxk + s * DPAIRS);
#pragma unroll
            for (int jj = 0; jj < 4; ++jj)
                dst[jj] = make_ulonglong2(row[2 * jj], row[2 * jj + 1]);
        } else {
            // direct output: sum over d of relu(z + b)
            float sum = 0.f;
#pragma unroll
            for (int j = 0; j < DPAIRS; ++j) {
                float lo, hi;
                unpack2(acc[si][j], lo, hi);
                sum += fmaxf(lo + bv, 0.f) + fmaxf(hi + bv, 0.f);
            }
            int oidx = (LAYER == 2) ? (128 + s) : (LAYER * 64 + (s - 64));
            outp[oidx] = sum;
        }
    }
    __syncwarp();  // writes visible before next layer reads
}

__global__ void __launch_bounds__(THREADS)
cin_kernel(const float* __restrict__ inputs,
           const float* __restrict__ w0, const float* __restrict__ w1,
           const float* __restrict__ w2,
           const float* __restrict__ pb0, const float* __restrict__ pb1,
           const float* __restrict__ pb2,
           float* __restrict__ out) {
    __shared__ __align__(16) unsigned long long sx0[NB][H0 * DPAIRS];   // 39 x 16 fp32
    __shared__ __align__(16) unsigned long long sxk[NB][64 * DPAIRS];   // 64 x 16 fp32

    int warp = threadIdx.x >> 5;
    int lane = threadIdx.x & 31;
    int b = blockIdx.x * NB + warp;

    // load x0 (624 floats = 156 float4) into sx0 and sxk (layer-0 xk = x0)
    const float4* src = (const float4*)(inputs + (size_t)b * (H0 * 16));
    float4* d0 = (float4*)sx0[warp];
    float4* dk = (float4*)sxk[warp];
    for (int i = lane; i < 156; i += 32) {
        float4 v = src[i];
        d0[i] = v;
        dk[i] = v;
    }
    __syncwarp();

    float* outp = out + (size_t)b * 256;
    do_layer<39, 0>(w0, pb0, sx0[warp], sxk[warp], lane, outp);
    do_layer<64, 1>(w1, pb1, sx0[warp], sxk[warp], lane, outp);
    do_layer<64, 2>(w2, pb2, sx0[warp], sxk[warp], lane, outp);
}

extern "C" void kernel_launch(void* const* d_in, const int* in_sizes, int n_in,
                              void* d_out, int out_size) {
    const float *inp = nullptr, *w0 = nullptr, *w1 = nullptr, *w2 = nullptr;
    const float *pb0 = nullptr, *pb1 = nullptr, *pb2 = nullptr;
    for (int i = 0; i < n_in; ++i) {
        const float* p = (const float*)d_in[i];
        int s = in_sizes[i];
        if (s == 2048 * 39 * 16) {
            inp = p;
        } else if (s == 39 * 39 * 128) {
            w0 = p;
        } else if (s == 39 * 64 * 128) {
            if (!w1) w1 = p; else w2 = p;
        } else if (s == 128) {
            if (!pb0) pb0 = p; else if (!pb1) pb1 = p; else pb2 = p;
        }
    }
    // 2048 batches / NB per block
    cin_kernel<<<2048 / NB, THREADS>>>(inp, w0, w1, w2, pb0, pb1, pb2, (float*)d_out);
}

// round 6
// speedup vs baseline: 5.8696x; 5.8696x over previous
#include <cuda_runtime.h>
#include <cuda_fp16.h>
#include <stdint.h>

// CIN via mma.sync (HMMA, no 'a'-gated ISA): z[(b,d),s] = sum_{h,k} x0*xk*W.
// CTA: 256 threads = 8 warps, 8 batches. warp = (s-group wy: 32 s) x (wx: 4 batches).
// K processed in 117 chunks of 64 (chunk = (layer, h)).

#define THREADS 256
#define NCHUNK 117
#define SW128(o) ((o) ^ ((((uint32_t)(o)) >> 3) & 0x70))

// Pre-swizzled f16 W tiles: [chunk][128 s x 64 k] = 16KB each, smem-image layout.
__device__ __half WPREP[NCHUNK][8192];

// dynamic smem layout (bytes)
#define OFF_W    0            // 2 x 16384 (double buffer)
#define OFF_XKT  32768        // 8 batches x [16 d][72] f32 = 36864
#define OFF_X0T  69632        // 8 batches x [16 d][40] f32 = 20480
#define OFF_BIAS 90112        // 384 f32
#define SMEM_TOTAL 91648
#define XKT_B 1152            // floats per batch (16*72)
#define X0T_B 640             // floats per batch (16*40)

__device__ __forceinline__ uint32_t smem_u32(const void* p) {
    uint32_t a;
    asm("{ .reg .u64 t; cvta.to.shared.u64 t, %1; cvt.u32.u64 %0, t; }" : "=r"(a) : "l"(p));
    return a;
}
__device__ __forceinline__ unsigned long long pack2(float lo, float hi) {
    unsigned long long d;
    asm("mov.b64 %0, {%1, %2};" : "=l"(d) : "f"(lo), "f"(hi));
    return d;
}
// f16x2 of (p * x0dup): h0 = lo element (k even), h1 = hi (k odd)
__device__ __forceinline__ uint32_t cvt_mul(unsigned long long p, unsigned long long x0dup) {
    uint32_t r;
    asm("{ .reg .b64 t; .reg .f32 lo, hi;\n\t"
        "mul.rn.f32x2 t, %1, %2;\n\t"
        "mov.b64 {lo, hi}, t;\n\t"
        "cvt.rn.f16x2.f32 %0, hi, lo; }"
        : "=r"(r) : "l"(p), "l"(x0dup));
    return r;
}
__device__ __forceinline__ void ldsm4(uint32_t* a, uint32_t addr) {
    asm volatile("ldmatrix.sync.aligned.m8n8.x4.shared.b16 {%0,%1,%2,%3}, [%4];"
                 : "=r"(a[0]), "=r"(a[1]), "=r"(a[2]), "=r"(a[3]) : "r"(addr));
}
__device__ __forceinline__ void mma16816(float* c, const uint32_t* a, uint32_t b0, uint32_t b1) {
    asm volatile(
        "mma.sync.aligned.m16n8k16.row.col.f32.f16.f16.f32 "
        "{%0,%1,%2,%3}, {%4,%5,%6,%7}, {%8,%9}, {%0,%1,%2,%3};"
        : "+f"(c[0]), "+f"(c[1]), "+f"(c[2]), "+f"(c[3])
        : "r"(a[0]), "r"(a[1]), "r"(a[2]), "r"(a[3]), "r"(b0), "r"(b1));
}
__device__ __forceinline__ void cp16(uint32_t dst, const void* src) {
    asm volatile("cp.async.ca.shared.global [%0], [%1], 16;" :: "r"(dst), "l"(src) : "memory");
}
__device__ __forceinline__ void cp_commit() {
    asm volatile("cp.async.commit_group;" ::: "memory");
}
template <int N>
__device__ __forceinline__ void cp_wait() {
    asm volatile("cp.async.wait_group %0;" :: "n"(N) : "memory");
}

// ---------------------------------------------------------------------------
// prep: W fp32 [h][k][s] -> per-chunk pre-swizzled f16 smem images [s-row 128B]
// ---------------------------------------------------------------------------
__global__ void __launch_bounds__(256) prep_w(const float* __restrict__ w0,
                                              const float* __restrict__ w1,
                                              const float* __restrict__ w2) {
    int idx = blockIdx.x * 256 + threadIdx.x;
    if (idx >= NCHUNK * 8192) return;
    int g = idx >> 13;          // chunk
    int i = idx & 8191;         // half index within 16KB tile
    int L = g / 39, h = g % 39;
    uint32_t o = SW128((uint32_t)(i * 2));   // logical byte offset (involution)
    int s = o >> 7;
    int k = (o & 127) >> 1;
    float v = 0.f;
    if (L == 0) {
        if (k < 39) v = w0[(h * 39 + k) * 128 + s];
    } else if (L == 1) {
        v = w1[(h * 64 + k) * 128 + s];
    } else {
        v = w2[(h * 64 + k) * 128 + s];
    }
    WPREP[g][i] = __float2half_rn(v);
}

// ---------------------------------------------------------------------------
// main fused kernel
// ---------------------------------------------------------------------------
__global__ void __launch_bounds__(THREADS, 2)
cin_hmma(const float* __restrict__ inputs,
         const float* __restrict__ pb0, const float* __restrict__ pb1,
         const float* __restrict__ pb2, float* __restrict__ out) {
    extern __shared__ char smem[];
    const uint32_t sb = smem_u32(smem);
    const int tid = threadIdx.x;
    const int lane = tid & 31;
    const int wid = tid >> 5;
    const int wy = wid >> 1;          // s-group: s in [wy*32, wy*32+32)
    const int wx = wid & 1;           // batch-group: local batches wx*4..wx*4+3
    const int gid = lane >> 2;        // 0..7
    const int tig = lane & 3;         // 0..3
    const int bstart = blockIdx.x * 8;

    float* xkt = (float*)(smem + OFF_XKT);
    float* x0t = (float*)(smem + OFF_X0T);
    float* sbias = (float*)(smem + OFF_BIAS);

    // prefetch chunk 0 into buf 0 (64B per thread)
    {
        uint32_t dst = sb + OFF_W + tid * 16;
        const __half* src = &WPREP[0][tid * 8];
#pragma unroll
        for (int j = 0; j < 4; ++j) cp16(dst + j * 4096, src + j * 2048);
        cp_commit();
    }

    // fills (overlap with prefetch)
    for (int i = tid; i < 8 * 624; i += THREADS) {
        int b = i / 624, r = i % 624, h = r / 16, d = r % 16;
        float v = inputs[(size_t)(bstart + b) * 624 + r];
        x0t[b * X0T_B + d * 40 + h] = v;
        xkt[b * XKT_B + d * 72 + h] = v;
    }
    for (int i = tid; i < 8 * 16 * 25; i += THREADS) {   // zero k=39..63 pad
        int b = i / 400, r = i % 400, d = r / 25, k = 39 + r % 25;
        xkt[b * XKT_B + d * 72 + k] = 0.f;
    }
    for (int i = tid; i < 384; i += THREADS)
        sbias[i] = (i < 128) ? pb0[i] : ((i < 256) ? pb1[i - 128] : pb2[i - 256]);

    float C[4][2][2][4];
#pragma unroll
    for (int b = 0; b < 4; ++b)
#pragma unroll
        for (int m = 0; m < 2; ++m)
#pragma unroll
            for (int n = 0; n < 2; ++n)
#pragma unroll
                for (int j = 0; j < 4; ++j) C[b][m][n][j] = 0.f;

    // ldmatrix lane geometry: matrix = lane>>3; row-in-16 = (lane&7) + ((lane>>3)&1)*8
    const int rowin = (lane & 7) + ((lane >> 3) & 1) * 8;
    const int lrow0 = wy * 32 + rowin;          // m-tile 0
    const int lcol = ((lane >> 4) & 1) * 16;    // k byte col within 16-k step

    int g = 0;
    for (int L = 0; L < 3; ++L) {
        for (int c = 0; c < 39; ++c, ++g) {
            if (g + 1 < NCHUNK) {
                uint32_t dst = sb + OFF_W + ((g + 1) & 1) * 16384 + tid * 16;
                const __half* src = &WPREP[g + 1][tid * 8];
#pragma unroll
                for (int j = 0; j < 4; ++j) cp16(dst + j * 4096, src + j * 2048);
            }
            cp_commit();
            cp_wait<1>();
            __syncthreads();   // chunk g W ready; xkt stable

            // x0 broadcast values for this chunk (h = c)
            unsigned long long x0d[4], x0d8[4];
#pragma unroll
            for (int bb = 0; bb < 4; ++bb) {
                const float* x0b = x0t + (wx * 4 + bb) * X0T_B;
                float a = x0b[gid * 40 + c];
                float a8 = x0b[(gid + 8) * 40 + c];
                x0d[bb] = pack2(a, a);
                x0d8[bb] = pack2(a8, a8);
            }
            const uint32_t wbase = sb + OFF_W + (g & 1) * 16384;

#pragma unroll
            for (int ks = 0; ks < 4; ++ks) {
                uint32_t A0[4], A1[4];
                ldsm4(A0, wbase + SW128((uint32_t)(lrow0 * 128 + ks * 32 + lcol)));
                ldsm4(A1, wbase + SW128((uint32_t)((lrow0 + 16) * 128 + ks * 32 + lcol)));
                const int kk = ks * 16 + 2 * tig;
#pragma unroll
                for (int bb = 0; bb < 4; ++bb) {
                    const float* xb = xkt + (wx * 4 + bb) * XKT_B;
                    unsigned long long p0 = *(const unsigned long long*)(xb + gid * 72 + kk);
                    unsigned long long p1 = *(const unsigned long long*)(xb + gid * 72 + kk + 8);
                    unsigned long long q0 = *(const unsigned long long*)(xb + (gid + 8) * 72 + kk);
                    unsigned long long q1 = *(const unsigned long long*)(xb + (gid + 8) * 72 + kk + 8);
                    uint32_t b00 = cvt_mul(p0, x0d[bb]);
                    uint32_t b01 = cvt_mul(p1, x0d[bb]);
                    uint32_t b10 = cvt_mul(q0, x0d8[bb]);
                    uint32_t b11 = cvt_mul(q1, x0d8[bb]);
                    mma16816(C[bb][0][0], A0, b00, b01);
                    mma16816(C[bb][0][1], A0, b10, b11);
                    mma16816(C[bb][1][0], A1, b00, b01);
                    mma16816(C[bb][1][1], A1, b10, b11);
                }
            }
            __syncthreads();   // done reading W buf[g&1] (and xkt) before reuse
        }

        // ---- layer epilogue ----
#pragma unroll
        for (int bb = 0; bb < 4; ++bb) {
            float* outp = out + (size_t)(bstart + wx * 4 + bb) * 256;
            float* xkb = xkt + (wx * 4 + bb) * XKT_B;
#pragma unroll
            for (int m = 0; m < 2; ++m) {
                const int s_r = wy * 32 + m * 16 + gid;      // and s_r + 8
                const float b_r = sbias[L * 128 + s_r];
                const float b_r8 = sbias[L * 128 + s_r + 8];
                float vr = 0.f, vr8 = 0.f;
#pragma unroll
                for (int n = 0; n < 2; ++n)
#pragma unroll
                    for (int j = 0; j < 2; ++j) {
                        const int d = 2 * tig + j + n * 8;
                        float z = fmaxf(C[bb][m][n][j] + b_r, 0.f);
                        float z8 = fmaxf(C[bb][m][n][2 + j] + b_r8, 0.f);
                        if (L < 2 && wy < 2) {
                            xkb[d * 72 + s_r] = z;
                            xkb[d * 72 + s_r + 8] = z8;
                        }
                        vr += z;
                        vr8 += z8;
                    }
                vr += __shfl_xor_sync(0xffffffffu, vr, 1);
                vr += __shfl_xor_sync(0xffffffffu, vr, 2);
                vr8 += __shfl_xor_sync(0xffffffffu, vr8, 1);
                vr8 += __shfl_xor_sync(0xffffffffu, vr8, 2);
                if (tig == 0) {
                    if (L == 2) {
                        outp[128 + s_r] = vr;
                        outp[128 + s_r + 8] = vr8;
                    } else if (wy >= 2) {
                        outp[L * 64 + s_r - 64] = vr;
                        outp[L * 64 + s_r - 64 + 8] = vr8;
                    }
                }
            }
#pragma unroll
            for (int m = 0; m < 2; ++m)
#pragma unroll
                for (int n = 0; n < 2; ++n)
#pragma unroll
                    for (int j = 0; j < 4; ++j) C[bb][m][n][j] = 0.f;
        }
        __syncthreads();   // new xkt visible before next layer
    }
}

extern "C" void kernel_launch(void* const* d_in, const int* in_sizes, int n_in,
                              void* d_out, int out_size) {
    const float *inp = nullptr, *w0 = nullptr, *w1 = nullptr, *w2 = nullptr;
    const float *pb0 = nullptr, *pb1 = nullptr, *pb2 = nullptr;
    for (int i = 0; i < n_in; ++i) {
        const float* p = (const float*)d_in[i];
        int s = in_sizes[i];
        if (s == 2048 * 39 * 16) {
            inp = p;
        } else if (s == 39 * 39 * 128) {
            w0 = p;
        } else if (s == 39 * 64 * 128) {
            if (!w1) w1 = p; else w2 = p;
        } else if (s == 128) {
            if (!pb0) pb0 = p; else if (!pb1) pb1 = p; else pb2 = p;
        }
    }
    cudaFuncSetAttribute(cin_hmma, cudaFuncAttributeMaxDynamicSharedMemorySize, SMEM_TOTAL);
    prep_w<<<(NCHUNK * 8192 + 255) / 256, 256>>>(w0, w1, w2);
    cin_hmma<<<256, THREADS, SMEM_TOTAL>>>(inp, pb0, pb1, pb2, (float*)d_out);
}

// round 10
// speedup vs baseline: 7.0205x; 1.1961x over previous
#include <cuda_runtime.h>
#include <cuda_fp16.h>
#include <stdint.h>

// CIN via mma.sync (HMMA): z[(b,d),s] = sum_{h,k} x0*xk*W.
// CTA: 256 threads = 8 warps, 8 batches. warp = (wy: 32 s) x (wx: 4 batches).
// K in 117 chunks of 64 (chunk = (layer, h)). xk in f16 with a k-permutation
// (xk ONLY; W unpermuted) so each lane's B fragment halves are one LDS.64.

#define THREADS 256
#define NCHUNK 117
#define SW128(o) ((o) ^ ((((uint32_t)(o)) >> 3) & 0x70))

// Pre-swizzled f16 W tiles: [chunk][128 s x 64 k] = 16KB each (k unpermuted).
__device__ __half WPREP[NCHUNK][8192];

// dynamic smem layout (bytes)
#define OFF_W    0            // 2 x 16384 double buffer
#define OFF_XKT  32768        // 8 b x 16 d x 80 f16 = 20480
#define OFF_X0   53248        // 8 b x 16 d x 40 u32 (f16x2 dup) = 20480
#define OFF_BIAS 73728        // 384 f32
#define SMEM_TOTAL 75264
#define XKT_B 1280            // f16 per batch (16*80)
#define X0_B 640              // u32 per batch (16*40)

// logical k (within 16) -> physical storage position for xk.
// Inverse: physical 4t+q holds logical 2t + 8*(q>>1) + (q&1), which is exactly
// the MMA B-slot order {2t,2t+1,2t+8,2t+9} for lane group t.
__host__ __device__ __forceinline__ int l2p(int l) {
    return (((l >> 1) & 3) << 2) | (((l >> 3) & 1) << 1) | (l & 1);
}

__device__ __forceinline__ uint32_t smem_u32(const void* p) {
    uint32_t a;
    asm("{ .reg .u64 t; cvta.to.shared.u64 t, %1; cvt.u32.u64 %0, t; }" : "=r"(a) : "l"(p));
    return a;
}
__device__ __forceinline__ uint32_t hmul2(uint32_t a, uint32_t b) {
    uint32_t r;
    asm("mul.rn.f16x2 %0, %1, %2;" : "=r"(r) : "r"(a), "r"(b));
    return r;
}
__device__ __forceinline__ void lds64(uint32_t& r0, uint32_t& r1, uint32_t addr) {
    asm volatile("ld.shared.v2.b32 {%0,%1}, [%2];" : "=r"(r0), "=r"(r1) : "r"(addr));
}
__device__ __forceinline__ uint32_t lds32(uint32_t addr) {
    uint32_t r;
    asm volatile("ld.shared.b32 %0, [%1];" : "=r"(r) : "r"(addr));
    return r;
}
__device__ __forceinline__ void ldsm4(uint32_t* a, uint32_t addr) {
    asm volatile("ldmatrix.sync.aligned.m8n8.x4.shared.b16 {%0,%1,%2,%3}, [%4];"
                 : "=r"(a[0]), "=r"(a[1]), "=r"(a[2]), "=r"(a[3]) : "r"(addr));
}
__device__ __forceinline__ void mma16816(float* c, const uint32_t* a, uint32_t b0, uint32_t b1) {
    asm volatile(
        "mma.sync.aligned.m16n8k16.row.col.f32.f16.f16.f32 "
        "{%0,%1,%2,%3}, {%4,%5,%6,%7}, {%8,%9}, {%0,%1,%2,%3};"
        : "+f"(c[0]), "+f"(c[1]), "+f"(c[2]), "+f"(c[3])
        : "r"(a[0]), "r"(a[1]), "r"(a[2]), "r"(a[3]), "r"(b0), "r"(b1));
}
__device__ __forceinline__ void cp16(uint32_t dst, const void* src) {
    asm volatile("cp.async.ca.shared.global [%0], [%1], 16;" :: "r"(dst), "l"(src) : "memory");
}
__device__ __forceinline__ void cp_commit() {
    asm volatile("cp.async.commit_group;" ::: "memory");
}
template <int N>
__device__ __forceinline__ void cp_wait() {
    asm volatile("cp.async.wait_group %0;" :: "n"(N) : "memory");
}

// ---------------------------------------------------------------------------
// prep: W fp32 [h][k][s] -> per-chunk pre-swizzled f16 smem images (k as-is)
// ---------------------------------------------------------------------------
__global__ void __launch_bounds__(256) prep_w(const float* __restrict__ w0,
                                              const float* __restrict__ w1,
                                              const float* __restrict__ w2) {
    int idx = blockIdx.x * 256 + threadIdx.x;
    if (idx >= NCHUNK * 8192) return;
    int g = idx >> 13;
    int i = idx & 8191;
    int L = g / 39, h = g % 39;
    uint32_t o = SW128((uint32_t)(i * 2));   // involution
    int s = o >> 7;
    int k = (o & 127) >> 1;                  // physical == logical k
    float v = 0.f;
    if (L == 0) {
        if (k < 39) v = w0[(h * 39 + k) * 128 + s];
    } else if (L == 1) {
        v = w1[(h * 64 + k) * 128 + s];
    } else {
        v = w2[(h * 64 + k) * 128 + s];
    }
    WPREP[g][i] = __float2half_rn(v);
}

// ---------------------------------------------------------------------------
// main fused kernel
// ---------------------------------------------------------------------------
__global__ void __launch_bounds__(THREADS, 2)
cin_hmma(const float* __restrict__ inputs,
         const float* __restrict__ pb0, const float* __restrict__ pb1,
         const float* __restrict__ pb2, float* __restrict__ out) {
    extern __shared__ char smem[];
    const uint32_t sb = smem_u32(smem);
    const int tid = threadIdx.x;
    const int lane = tid & 31;
    const int wid = tid >> 5;
    const int wy = wid >> 1;          // s-group: s in [wy*32, wy*32+32)
    const int wx = wid & 1;           // batch-group: local batches wx*4..wx*4+3
    const int gid = lane >> 2;        // 0..7  (d row / B n index)
    const int tig = lane & 3;         // 0..3
    const int bstart = blockIdx.x * 8;

    __half* xkt = (__half*)(smem + OFF_XKT);
    uint32_t* x0d = (uint32_t*)(smem + OFF_X0);
    float* sbias = (float*)(smem + OFF_BIAS);

    // prefetch chunk 0 into buf 0
    {
        uint32_t dst = sb + OFF_W + tid * 16;
        const __half* src = &WPREP[0][tid * 8];
#pragma unroll
        for (int j = 0; j < 4; ++j) cp16(dst + j * 4096, src + j * 2048);
        cp_commit();
    }

    // zero xkt (covers layer-0 k pad), then fill
    for (int i = tid; i < 5120; i += THREADS) ((uint32_t*)xkt)[i] = 0u;
    __syncthreads();
    for (int i = tid; i < 8 * 624; i += THREADS) {
        int b = i / 624, r = i % 624, h = r / 16, d = r % 16;
        float v = inputs[(size_t)(bstart + b) * 624 + r];
        uint16_t hb = __half_as_ushort(__float2half_rn(v));
        x0d[b * X0_B + d * 40 + h] = (uint32_t)hb * 0x10001u;
        int pos = (h & ~15) | l2p(h & 15);
        xkt[b * XKT_B + d * 80 + pos] = __ushort_as_half(hb);
    }
    for (int i = tid; i < 384; i += THREADS)
        sbias[i] = (i < 128) ? pb0[i] : ((i < 256) ? pb1[i - 128] : pb2[i - 256]);

    float C[4][2][2][4];
#pragma unroll
    for (int b = 0; b < 4; ++b)
#pragma unroll
        for (int m = 0; m < 2; ++m)
#pragma unroll
            for (int n = 0; n < 2; ++n)
#pragma unroll
                for (int j = 0; j < 4; ++j) C[b][m][n][j] = 0.f;

    // ldmatrix lane geometry
    const int rowin = (lane & 7) + ((lane >> 3) & 1) * 8;
    const int lrow0 = wy * 32 + rowin;
    const int lcol = ((lane >> 4) & 1) * 16;

    // per-lane xk byte offsets (within a batch): d-row gid, phys base 4*tig
    const uint32_t xk_lane_lo = (uint32_t)(gid * 160 + tig * 8);
    const uint32_t xk_lane_hi = xk_lane_lo + 8 * 160;
    const uint32_t xkt_base = sb + OFF_XKT + wx * 4 * (XKT_B * 2);
    const uint32_t x0_base = sb + OFF_X0 + wx * 4 * (X0_B * 4);

    int g = 0;
    for (int L = 0; L < 3; ++L) {
        for (int c = 0; c < 39; ++c, ++g) {
            if (g + 1 < NCHUNK) {
                uint32_t dst = sb + OFF_W + ((g + 1) & 1) * 16384 + tid * 16;
                const __half* src = &WPREP[g + 1][tid * 8];
#pragma unroll
                for (int j = 0; j < 4; ++j) cp16(dst + j * 4096, src + j * 2048);
            }
            cp_commit();
            cp_wait<1>();
            __syncthreads();   // chunk g W ready; xkt stable

            // x0 f16x2 dups for h = c  (rows gid and gid+8)
            uint32_t x0lo[4], x0hi[4];
#pragma unroll
            for (int bb = 0; bb < 4; ++bb) {
                uint32_t xa = x0_base + (bb * X0_B + gid * 40 + c) * 4;
                x0lo[bb] = lds32(xa);
                x0hi[bb] = lds32(xa + 8 * 40 * 4);
            }
            const uint32_t wbase = sb + OFF_W + (g & 1) * 16384;

#pragma unroll
            for (int ks = 0; ks < 4; ++ks) {
                uint32_t A0[4], A1[4];
                ldsm4(A0, wbase + SW128((uint32_t)(lrow0 * 128 + ks * 32 + lcol)));
                ldsm4(A1, wbase + SW128((uint32_t)((lrow0 + 16) * 128 + ks * 32 + lcol)));
#pragma unroll
                for (int bb = 0; bb < 4; ++bb) {
                    uint32_t xb = xkt_base + bb * (XKT_B * 2) + ks * 32;
                    uint32_t r0, r1, q0, q1;
                    lds64(r0, r1, xb + xk_lane_lo);
                    lds64(q0, q1, xb + xk_lane_hi);
                    uint32_t b00 = hmul2(r0, x0lo[bb]);
                    uint32_t b01 = hmul2(r1, x0lo[bb]);
                    uint32_t b10 = hmul2(q0, x0hi[bb]);
                    uint32_t b11 = hmul2(q1, x0hi[bb]);
                    mma16816(C[bb][0][0], A0, b00, b01);
                    mma16816(C[bb][0][1], A0, b10, b11);
                    mma16816(C[bb][1][0], A1, b00, b01);
                    mma16816(C[bb][1][1], A1, b10, b11);
                }
            }
            __syncthreads();   // done reading W buf and xkt before reuse
        }

        // ---- layer epilogue ----
#pragma unroll
        for (int bb = 0; bb < 4; ++bb) {
            float* outp = out + (size_t)(bstart + wx * 4 + bb) * 256;
            __half* xkb = xkt + (wx * 4 + bb) * XKT_B;
#pragma unroll
            for (int m = 0; m < 2; ++m) {
                const int s_r = wy * 32 + m * 16 + gid;      // and s_r + 8
                const float b_r = sbias[L * 128 + s_r];
                const float b_r8 = sbias[L * 128 + s_r + 8];
                float vr = 0.f, vr8 = 0.f;
                const int pos = (s_r & ~15) | l2p(s_r & 15);
                const int pos8 = ((s_r + 8) & ~15) | l2p((s_r + 8) & 15);
#pragma unroll
                for (int n = 0; n < 2; ++n)
#pragma unroll
                    for (int j = 0; j < 2; ++j) {
                        const int d = 2 * tig + j + n * 8;
                        float z = fmaxf(C[bb][m][n][j] + b_r, 0.f);
                        float z8 = fmaxf(C[bb][m][n][2 + j] + b_r8, 0.f);
                        if (L < 2 && wy < 2) {
                            xkb[d * 80 + pos] = __float2half_rn(z);
                            xkb[d * 80 + pos8] = __float2half_rn(z8);
                        }
                        vr += z;
                        vr8 += z8;
                    }
                vr += __shfl_xor_sync(0xffffffffu, vr, 1);
                vr += __shfl_xor_sync(0xffffffffu, vr, 2);
                vr8 += __shfl_xor_sync(0xffffffffu, vr8, 1);
                vr8 += __shfl_xor_sync(0xffffffffu, vr8, 2);
                if (tig == 0) {
                    if (L == 2) {
                        outp[128 + s_r] = vr;
                        outp[128 + s_r + 8] = vr8;
                    } else if (wy >= 2) {
                        outp[L * 64 + s_r - 64] = vr;
                        outp[L * 64 + s_r - 64 + 8] = vr8;
                    }
                }
            }
#pragma unroll
            for (int m = 0; m < 2; ++m)
#pragma unroll
                for (int n = 0; n < 2; ++n)
#pragma unroll
                    for (int j = 0; j < 4; ++j) C[bb][m][n][j] = 0.f;
        }
        __syncthreads();   // new xkt visible before next layer
    }
}

extern "C" void kernel_launch(void* const* d_in, const int* in_sizes, int n_in,
                              void* d_out, int out_size) {
    const float *inp = nullptr, *w0 = nullptr, *w1 = nullptr, *w2 = nullptr;
    const float *pb0 = nullptr, *pb1 = nullptr, *pb2 = nullptr;
    for (int i = 0; i < n_in; ++i) {
        const float* p = (const float*)d_in[i];
        int s = in_sizes[i];
        if (s == 2048 * 39 * 16) {
            inp = p;
        } else if (s == 39 * 39 * 128) {
            w0 = p;
        } else if (s == 39 * 64 * 128) {
            if (!w1) w1 = p; else w2 = p;
        } else if (s == 128) {
            if (!pb0) pb0 = p; else if (!pb1) pb1 = p; else pb2 = p;
        }
    }
    cudaFuncSetAttribute(cin_hmma, cudaFuncAttributeMaxDynamicSharedMemorySize, SMEM_TOTAL);
    prep_w<<<(NCHUNK * 8192 + 255) / 256, 256>>>(w0, w1, w2);
    cin_hmma<<<256, THREADS, SMEM_TOTAL>>>(inp, pb0, pb1, pb2, (float*)d_out);
}

// round 11
// speedup vs baseline: 7.0522x; 1.0045x over previous
#include <cuda_runtime.h>
#include <cuda_fp16.h>
#include <stdint.h>

// CIN via mma.sync (HMMA): z[(b,d),s] = sum_{h,k} x0*xk*W.
// CTA: 256 threads = 8 warps, 8 batches. warp = (wy: 32 s) x (wx: 4 batches).
// K in 117 chunks of 64 (chunk = (layer, h)). xk f16 with a full-64 k-perm so a
// lane's B halves for a ks-PAIR are one lds128. Triple-buffered W, 1 barrier/chunk.

#define THREADS 256
#define NCHUNK 117
#define SW128(o) ((o) ^ ((((uint32_t)(o)) >> 3) & 0x70))

// Pre-swizzled f16 W tiles: [chunk][128 s x 64 k] = 16KB each (k logical order).
__device__ __half WPREP[NCHUNK][8192];

// dynamic smem layout (bytes)
#define OFF_W    0            // 3 x 16384 triple buffer
#define OFF_XKT  49152        // 8 b x 16 d x 72 f16 = 18432
#define OFF_X0   67584        // 8 b x 16 d x 44 u32 (f16x2 dup) = 22528
#define OFF_BIAS 90112        // 384 f32
#define SMEM_TOTAL 91648
#define XKT_B 1152            // f16 per batch (16*72), row stride 144B
#define X0_B 704              // u32 per batch (16*44), row stride 176B

// logical k (0..63) -> physical f16 position within a 64-slot row.
// storage u32 idx = t*8 + ks*2 + r  (t=(k>>1)&3, r=(k>>3)&1, ks=(k>>4)&3, b=k&1)
// => one lds128 at byte t*32 + p*16 yields [ks(2p) r0, ks(2p) r1, ks(2p+1) r0, ks(2p+1) r1].
__host__ __device__ __forceinline__ int pos64(int k) {
    return ((k & 6) << 3) | ((k >> 2) & 12) | ((k >> 2) & 2) | (k & 1);
}

__device__ __forceinline__ uint32_t smem_u32(const void* p) {
    uint32_t a;
    asm("{ .reg .u64 t; cvta.to.shared.u64 t, %1; cvt.u32.u64 %0, t; }" : "=r"(a) : "l"(p));
    return a;
}
__device__ __forceinline__ uint32_t hmul2(uint32_t a, uint32_t b) {
    uint32_t r;
    asm("mul.rn.f16x2 %0, %1, %2;" : "=r"(r) : "r"(a), "r"(b));
    return r;
}
__device__ __forceinline__ uint4 lds128(uint32_t addr) {
    uint4 v;
    asm volatile("ld.shared.v4.b32 {%0,%1,%2,%3}, [%4];"
                 : "=r"(v.x), "=r"(v.y), "=r"(v.z), "=r"(v.w) : "r"(addr));
    return v;
}
__device__ __forceinline__ uint32_t lds32(uint32_t addr) {
    uint32_t r;
    asm volatile("ld.shared.b32 %0, [%1];" : "=r"(r) : "r"(addr));
    return r;
}
__device__ __forceinline__ void ldsm4(uint32_t* a, uint32_t addr) {
    asm volatile("ldmatrix.sync.aligned.m8n8.x4.shared.b16 {%0,%1,%2,%3}, [%4];"
                 : "=r"(a[0]), "=r"(a[1]), "=r"(a[2]), "=r"(a[3]) : "r"(addr));
}
__device__ __forceinline__ void mma16816(float* c, const uint32_t* a, uint32_t b0, uint32_t b1) {
    asm volatile(
        "mma.sync.aligned.m16n8k16.row.col.f32.f16.f16.f32 "
        "{%0,%1,%2,%3}, {%4,%5,%6,%7}, {%8,%9}, {%0,%1,%2,%3};"
        : "+f"(c[0]), "+f"(c[1]), "+f"(c[2]), "+f"(c[3])
        : "r"(a[0]), "r"(a[1]), "r"(a[2]), "r"(a[3]), "r"(b0), "r"(b1));
}
__device__ __forceinline__ void cp16(uint32_t dst, const void* src) {
    asm volatile("cp.async.ca.shared.global [%0], [%1], 16;" :: "r"(dst), "l"(src) : "memory");
}
__device__ __forceinline__ void cp_commit() {
    asm volatile("cp.async.commit_group;" ::: "memory");
}
template <int N>
__device__ __forceinline__ void cp_wait() {
    asm volatile("cp.async.wait_group %0;" :: "n"(N) : "memory");
}

// ---------------------------------------------------------------------------
// prep: W fp32 [h][k][s] -> per-chunk pre-swizzled f16 smem images (k logical)
// ---------------------------------------------------------------------------
__global__ void __launch_bounds__(256) prep_w(const float* __restrict__ w0,
                                              const float* __restrict__ w1,
                                              const float* __restrict__ w2) {
    int idx = blockIdx.x * 256 + threadIdx.x;
    if (idx >= NCHUNK * 8192) return;
    int g = idx >> 13;
    int i = idx & 8191;
    int L = g / 39, h = g % 39;
    uint32_t o = SW128((uint32_t)(i * 2));   // involution
    int s = o >> 7;
    int k = (o & 127) >> 1;
    float v = 0.f;
    if (L == 0) {
        if (k < 39) v = w0[(h * 39 + k) * 128 + s];
    } else if (L == 1) {
        v = w1[(h * 64 + k) * 128 + s];
    } else {
        v = w2[(h * 64 + k) * 128 + s];
    }
    WPREP[g][i] = __float2half_rn(v);
}

// ---------------------------------------------------------------------------
// main fused kernel
// ---------------------------------------------------------------------------
__global__ void __launch_bounds__(THREADS, 2)
cin_hmma(const float* __restrict__ inputs,
         const float* __restrict__ pb0, const float* __restrict__ pb1,
         const float* __restrict__ pb2, float* __restrict__ out) {
    extern __shared__ char smem[];
    const uint32_t sb = smem_u32(smem);
    const int tid = threadIdx.x;
    const int lane = tid & 31;
    const int wid = tid >> 5;
    const int wy = wid >> 1;          // s-group: s in [wy*32, wy*32+32)
    const int wx = wid & 1;           // batch-group: local batches wx*4..wx*4+3
    const int gid = lane >> 2;        // 0..7  (d row / B n index)
    const int tig = lane & 3;         // 0..3
    const int bstart = blockIdx.x * 8;

    __half* xkt = (__half*)(smem + OFF_XKT);
    uint32_t* x0d = (uint32_t*)(smem + OFF_X0);
    float* sbias = (float*)(smem + OFF_BIAS);

    // prefetch chunk 0 into buf 0
    {
        uint32_t dst = sb + OFF_W + tid * 16;
        const __half* src = &WPREP[0][tid * 8];
#pragma unroll
        for (int j = 0; j < 4; ++j) cp16(dst + j * 4096, src + j * 2048);
        cp_commit();
    }

    // zero xkt (covers layer-0 k pad + stride pad), then fill
    for (int i = tid; i < 4608; i += THREADS) ((uint32_t*)xkt)[i] = 0u;
    __syncthreads();
    for (int i = tid; i < 8 * 624; i += THREADS) {
        int b = i / 624, r = i % 624, h = r / 16, d = r % 16;
        float v = inputs[(size_t)(bstart + b) * 624 + r];
        uint16_t hb = __half_as_ushort(__float2half_rn(v));
        x0d[b * X0_B + d * 44 + h] = (uint32_t)hb * 0x10001u;
        xkt[b * XKT_B + d * 72 + pos64(h)] = __ushort_as_half(hb);
    }
    for (int i = tid; i < 384; i += THREADS)
        sbias[i] = (i < 128) ? pb0[i] : ((i < 256) ? pb1[i - 128] : pb2[i - 256]);
    __syncthreads();   // fills complete before pre-barrier B loads of chunk 0

    float C[4][2][2][4];
#pragma unroll
    for (int b = 0; b < 4; ++b)
#pragma unroll
        for (int m = 0; m < 2; ++m)
#pragma unroll
            for (int n = 0; n < 2; ++n)
#pragma unroll
                for (int j = 0; j < 4; ++j) C[b][m][n][j] = 0.f;

    // ldmatrix lane geometry
    const int rowin = (lane & 7) + ((lane >> 3) & 1) * 8;
    const int lrow0 = wy * 32 + rowin;
    const int lcol = ((lane >> 4) & 1) * 16;

    // per-lane B addresses: d-row gid, quad tig
    const uint32_t xk_lane = (uint32_t)(gid * 144 + tig * 32);
    const uint32_t xkt_base = sb + OFF_XKT + wx * 4 * 2304;   // batch stride 2304B
    const uint32_t x0_base = sb + OFF_X0 + wx * 4 * 2816;     // batch stride 2816B

    int g = 0, buf = 0;
    for (int L = 0; L < 3; ++L) {
        for (int c = 0; c < 39; ++c, ++g) {
            int nbuf = buf + 1;
            if (nbuf == 3) nbuf = 0;
            if (g + 1 < NCHUNK) {
                uint32_t dst = sb + OFF_W + nbuf * 16384 + tid * 16;
                const __half* src = &WPREP[g + 1][tid * 8];
#pragma unroll
                for (int j = 0; j < 4; ++j) cp16(dst + j * 4096, src + j * 2048);
            }
            cp_commit();

            // --- pre-barrier loads (layer-stable smem) ---
            uint32_t x0lo[4], x0hi[4];
            uint4 r0lo[4], r0hi[4];   // ks-pair 0 raw B
#pragma unroll
            for (int bb = 0; bb < 4; ++bb) {
                uint32_t xa = x0_base + (bb * X0_B + gid * 44 + c) * 4;
                x0lo[bb] = lds32(xa);
                x0hi[bb] = lds32(xa + 1408);
                uint32_t xb = xkt_base + bb * 2304 + xk_lane;
                r0lo[bb] = lds128(xb);
                r0hi[bb] = lds128(xb + 1152);
            }

            cp_wait<1>();
            __syncthreads();   // W chunk g resident in buf

            const uint32_t wbase = sb + OFF_W + buf * 16384;

            // ---- ks-pair 0 (ks = 0,1) ----
            {
                uint32_t A0[4], A1[4], A2[4], A3[4];
                ldsm4(A0, wbase + SW128((uint32_t)(lrow0 * 128 + 0 + lcol)));
                ldsm4(A1, wbase + SW128((uint32_t)((lrow0 + 16) * 128 + 0 + lcol)));
                ldsm4(A2, wbase + SW128((uint32_t)(lrow0 * 128 + 32 + lcol)));
                ldsm4(A3, wbase + SW128((uint32_t)((lrow0 + 16) * 128 + 32 + lcol)));
#pragma unroll
                for (int bb = 0; bb < 4; ++bb) {
                    uint32_t b00 = hmul2(r0lo[bb].x, x0lo[bb]);
                    uint32_t b01 = hmul2(r0lo[bb].y, x0lo[bb]);
                    uint32_t b10 = hmul2(r0hi[bb].x, x0hi[bb]);
                    uint32_t b11 = hmul2(r0hi[bb].y, x0hi[bb]);
                    mma16816(C[bb][0][0], A0, b00, b01);
                    mma16816(C[bb][0][1], A0, b10, b11);
                    mma16816(C[bb][1][0], A1, b00, b01);
                    mma16816(C[bb][1][1], A1, b10, b11);
                }
#pragma unroll
                for (int bb = 0; bb < 4; ++bb) {
                    uint32_t b00 = hmul2(r0lo[bb].z, x0lo[bb]);
                    uint32_t b01 = hmul2(r0lo[bb].w, x0lo[bb]);
                    uint32_t b10 = hmul2(r0hi[bb].z, x0hi[bb]);
                    uint32_t b11 = hmul2(r0hi[bb].w, x0hi[bb]);
                    mma16816(C[bb][0][0], A2, b00, b01);
                    mma16816(C[bb][0][1], A2, b10, b11);
                    mma16816(C[bb][1][0], A3, b00, b01);
                    mma16816(C[bb][1][1], A3, b10, b11);
                }
            }
            // ---- ks-pair 1 (ks = 2,3) ----
            {
                uint4 r1lo[4], r1hi[4];
#pragma unroll
                for (int bb = 0; bb < 4; ++bb) {
                    uint32_t xb = xkt_base + bb * 2304 + xk_lane + 16;
                    r1lo[bb] = lds128(xb);
                    r1hi[bb] = lds128(xb + 1152);
                }
                uint32_t A0[4], A1[4], A2[4], A3[4];
                ldsm4(A0, wbase + SW128((uint32_t)(lrow0 * 128 + 64 + lcol)));
                ldsm4(A1, wbase + SW128((uint32_t)((lrow0 + 16) * 128 + 64 + lcol)));
                ldsm4(A2, wbase + SW128((uint32_t)(lrow0 * 128 + 96 + lcol)));
                ldsm4(A3, wbase + SW128((uint32_t)((lrow0 + 16) * 128 + 96 + lcol)));
#pragma unroll
                for (int bb = 0; bb < 4; ++bb) {
                    uint32_t b00 = hmul2(r1lo[bb].x, x0lo[bb]);
                    uint32_t b01 = hmul2(r1lo[bb].y, x0lo[bb]);
                    uint32_t b10 = hmul2(r1hi[bb].x, x0hi[bb]);
                    uint32_t b11 = hmul2(r1hi[bb].y, x0hi[bb]);
                    mma16816(C[bb][0][0], A0, b00, b01);
                    mma16816(C[bb][0][1], A0, b10, b11);
                    mma16816(C[bb][1][0], A1, b00, b01);
                    mma16816(C[bb][1][1], A1, b10, b11);
                }
#pragma unroll
                for (int bb = 0; bb < 4; ++bb) {
                    uint32_t b00 = hmul2(r1lo[bb].z, x0lo[bb]);
                    uint32_t b01 = hmul2(r1lo[bb].w, x0lo[bb]);
                    uint32_t b10 = hmul2(r1hi[bb].z, x0hi[bb]);
                    uint32_t b11 = hmul2(r1hi[bb].w, x0hi[bb]);
                    mma16816(C[bb][0][0], A2, b00, b01);
                    mma16816(C[bb][0][1], A2, b10, b11);
                    mma16816(C[bb][1][0], A3, b00, b01);
                    mma16816(C[bb][1][1], A3, b10, b11);
                }
            }
            buf = nbuf;
            // no trailing barrier: triple-buffered W, xkt read-only within layer
        }

        __syncthreads();   // all MMA reads of xkt done before epilogue overwrites

        // ---- layer epilogue ----
#pragma unroll
        for (int bb = 0; bb < 4; ++bb) {
            float* outp = out + (size_t)(bstart + wx * 4 + bb) * 256;
            __half* xkb = xkt + (wx * 4 + bb) * XKT_B;
#pragma unroll
            for (int m = 0; m < 2; ++m) {
                const int s_r = wy * 32 + m * 16 + gid;      // and s_r + 8
                const float b_r = sbias[L * 128 + s_r];
                const float b_r8 = sbias[L * 128 + s_r + 8];
                float vr = 0.f, vr8 = 0.f;
                const int pos = pos64(s_r & 63);
                const int pos8 = pos64((s_r + 8) & 63);
#pragma unroll
                for (int n = 0; n < 2; ++n)
#pragma unroll
                    for (int j = 0; j < 2; ++j) {
                        const int d = 2 * tig + j + n * 8;
                        float z = fmaxf(C[bb][m][n][j] + b_r, 0.f);
                        float z8 = fmaxf(C[bb][m][n][2 + j] + b_r8, 0.f);
                        if (L < 2 && wy < 2) {
                            xkb[d * 72 + pos] = __float2half_rn(z);
                            xkb[d * 72 + pos8] = __float2half_rn(z8);
                        }
                        vr += z;
                        vr8 += z8;
                    }
                vr += __shfl_xor_sync(0xffffffffu, vr, 1);
                vr += __shfl_xor_sync(0xffffffffu, vr, 2);
                vr8 += __shfl_xor_sync(0xffffffffu, vr8, 1);
                vr8 += __shfl_xor_sync(0xffffffffu, vr8, 2);
                if (tig == 0) {
                    if (L == 2) {
                        outp[128 + s_r] = vr;
                        outp[128 + s_r + 8] = vr8;
                    } else if (wy >= 2) {
                        outp[L * 64 + s_r - 64] = vr;
                        outp[L * 64 + s_r - 64 + 8] = vr8;
                    }
                }
            }
#pragma unroll
            for (int m = 0; m < 2; ++m)
#pragma unroll
                for (int n = 0; n < 2; ++n)
#pragma unroll
                    for (int j = 0; j < 4; ++j) C[bb][m][n][j] = 0.f;
        }
        __syncthreads();   // new xkt visible before next layer's pre-barrier loads
    }
}

extern "C" void kernel_launch(void* const* d_in, const int* in_sizes, int n_in,
                              void* d_out, int out_size) {
    const float *inp = nullptr, *w0 = nullptr, *w1 = nullptr, *w2 = nullptr;
    const float *pb0 = nullptr, *pb1 = nullptr, *pb2 = nullptr;
    for (int i = 0; i < n_in; ++i) {
        const float* p = (const float*)d_in[i];
        int s = in_sizes[i];
        if (s == 2048 * 39 * 16) {
            inp = p;
        } else if (s == 39 * 39 * 128) {
            w0 = p;
        } else if (s == 39 * 64 * 128) {
            if (!w1) w1 = p; else w2 = p;
        } else if (s == 128) {
            if (!pb0) pb0 = p; else if (!pb1) pb1 = p; else pb2 = p;
        }
    }
    cudaFuncSetAttribute(cin_hmma, cudaFuncAttributeMaxDynamicSharedMemorySize, SMEM_TOTAL);
    prep_w<<<(NCHUNK * 8192 + 255) / 256, 256>>>(w0, w1, w2);
    cin_hmma<<<256, THREADS, SMEM_TOTAL>>>(inp, pb0, pb1, pb2, (float*)d_out);
}

// round 12
// speedup vs baseline: 7.7978x; 1.1057x over previous
#include <cuda_runtime.h>
#include <cuda_fp16.h>
#include <stdint.h>

// CIN via mma.sync (HMMA): z[(b,d),s] = sum_{h,k} x0*xk*W.
// CTA: 256 threads = 8 warps, 8 batches. warp = (wy: 32 s) x (wx: 4 batches).
// K in 117 chunks (chunk = (layer, h)); layer 0 weights are symmetry-folded
// upper-triangle (Wf[h,k]=W[h,k]+W[k,h], k>=h) so chunk h only runs
// ks-slabs [h>>4 .. 2]; layers 1/2 run [0..3]. Triple-buffered W staging.

#define THREADS 256
#define NCHUNK 117
#define SW128(o) ((o) ^ ((((uint32_t)(o)) >> 3) & 0x70))

// Pre-swizzled f16 W tiles: [chunk][128 s x 64 k] = 16KB each.
__device__ __half WPREP[NCHUNK][8192];

// dynamic smem layout (bytes)
#define OFF_W    0            // 3 x 16384 triple buffer
#define OFF_XKT  49152        // 8 b x 16 d x 72 f16 = 18432
#define OFF_X0   67584        // 8 b x 16 d x 44 u32 (f16x2 dup) = 22528
#define OFF_BIAS 90112        // 384 f32
#define SMEM_TOTAL 91648
#define XKT_B 1152            // f16 per batch (16*72), row stride 144B
#define X0_B 704              // u32 per batch (16*44), row stride 176B

// logical k (0..63) -> physical f16 position within a 64-slot row.
// u32 index = t*8 + ks*2 + r  (t=(k>>1)&3, ks=k>>4, r=(k>>3)&1, b=k&1):
// per (row, ks) a lane's {b0,b1} raw pair is one lds64 at byte t*32 + ks*8.
__host__ __device__ __forceinline__ int pos64(int k) {
    return ((k & 6) << 3) | ((k >> 2) & 12) | ((k >> 2) & 2) | (k & 1);
}

__device__ __forceinline__ uint32_t smem_u32(const void* p) {
    uint32_t a;
    asm("{ .reg .u64 t; cvta.to.shared.u64 t, %1; cvt.u32.u64 %0, t; }" : "=r"(a) : "l"(p));
    return a;
}
__device__ __forceinline__ uint32_t hmul2(uint32_t a, uint32_t b) {
    uint32_t r;
    asm("mul.rn.f16x2 %0, %1, %2;" : "=r"(r) : "r"(a), "r"(b));
    return r;
}
__device__ __forceinline__ void lds64(uint32_t& r0, uint32_t& r1, uint32_t addr) {
    asm volatile("ld.shared.v2.b32 {%0,%1}, [%2];" : "=r"(r0), "=r"(r1) : "r"(addr));
}
__device__ __forceinline__ uint32_t lds32(uint32_t addr) {
    uint32_t r;
    asm volatile("ld.shared.b32 %0, [%1];" : "=r"(r) : "r"(addr));
    return r;
}
__device__ __forceinline__ void ldsm4(uint32_t* a, uint32_t addr) {
    asm volatile("ldmatrix.sync.aligned.m8n8.x4.shared.b16 {%0,%1,%2,%3}, [%4];"
                 : "=r"(a[0]), "=r"(a[1]), "=r"(a[2]), "=r"(a[3]) : "r"(addr));
}
__device__ __forceinline__ void mma16816(float* c, const uint32_t* a, uint32_t b0, uint32_t b1) {
    asm volatile(
        "mma.sync.aligned.m16n8k16.row.col.f32.f16.f16.f32 "
        "{%0,%1,%2,%3}, {%4,%5,%6,%7}, {%8,%9}, {%0,%1,%2,%3};"
        : "+f"(c[0]), "+f"(c[1]), "+f"(c[2]), "+f"(c[3])
        : "r"(a[0]), "r"(a[1]), "r"(a[2]), "r"(a[3]), "r"(b0), "r"(b1));
}
__device__ __forceinline__ void cp16(uint32_t dst, const void* src) {
    asm volatile("cp.async.ca.shared.global [%0], [%1], 16;" :: "r"(dst), "l"(src) : "memory");
}
__device__ __forceinline__ void cp_commit() {
    asm volatile("cp.async.commit_group;" ::: "memory");
}
template <int N>
__device__ __forceinline__ void cp_wait() {
    asm volatile("cp.async.wait_group %0;" :: "n"(N) : "memory");
}

// ---------------------------------------------------------------------------
// prep: W fp32 [h][k][s] -> per-chunk pre-swizzled f16 smem images.
// Layer 0 is symmetry-folded: Wf[h][k] = W[h][k]+W[k][h] (k>h), W[h][h] (k==h),
// 0 (k<h). Layers 1/2 unchanged.
// ---------------------------------------------------------------------------
__global__ void __launch_bounds__(256) prep_w(const float* __restrict__ w0,
                                              const float* __restrict__ w1,
                                              const float* __restrict__ w2) {
    int idx = blockIdx.x * 256 + threadIdx.x;
    if (idx >= NCHUNK * 8192) return;
    int g = idx >> 13;
    int i = idx & 8191;
    int L = g / 39, h = g % 39;
    uint32_t o = SW128((uint32_t)(i * 2));   // involution
    int s = o >> 7;
    int k = (o & 127) >> 1;
    float v = 0.f;
    if (L == 0) {
        if (k < 39 && k >= h) {
            v = w0[(h * 39 + k) * 128 + s];
            if (k > h) v += w0[(k * 39 + h) * 128 + s];
        }
    } else if (L == 1) {
        v = w1[(h * 64 + k) * 128 + s];
    } else {
        v = w2[(h * 64 + k) * 128 + s];
    }
    WPREP[g][i] = __float2half_rn(v);
}

// ---------------------------------------------------------------------------
// main fused kernel
// ---------------------------------------------------------------------------
__global__ void __launch_bounds__(THREADS, 2)
cin_hmma(const float* __restrict__ inputs,
         const float* __restrict__ pb0, const float* __restrict__ pb1,
         const float* __restrict__ pb2, float* __restrict__ out) {
    extern __shared__ char smem[];
    const uint32_t sb = smem_u32(smem);
    const int tid = threadIdx.x;
    const int lane = tid & 31;
    const int wid = tid >> 5;
    const int wy = wid >> 1;          // s-group: s in [wy*32, wy*32+32)
    const int wx = wid & 1;           // batch-group: local batches wx*4..wx*4+3
    const int gid = lane >> 2;        // 0..7  (d row / B n index)
    const int tig = lane & 3;         // 0..3
    const int bstart = blockIdx.x * 8;

    __half* xkt = (__half*)(smem + OFF_XKT);
    uint32_t* x0d = (uint32_t*)(smem + OFF_X0);
    float* sbias = (float*)(smem + OFF_BIAS);

    // prefetch chunk 0 into buf 0
    {
        uint32_t dst = sb + OFF_W + tid * 16;
        const __half* src = &WPREP[0][tid * 8];
#pragma unroll
        for (int j = 0; j < 4; ++j) cp16(dst + j * 4096, src + j * 2048);
        cp_commit();
    }

    // zero xkt (covers layer-0 k pad + stride pad), then fill
    for (int i = tid; i < 4608; i += THREADS) ((uint32_t*)xkt)[i] = 0u;
    __syncthreads();
    for (int i = tid; i < 8 * 624; i += THREADS) {
        int b = i / 624, r = i % 624, h = r / 16, d = r % 16;
        float v = inputs[(size_t)(bstart + b) * 624 + r];
        uint16_t hb = __half_as_ushort(__float2half_rn(v));
        x0d[b * X0_B + d * 44 + h] = (uint32_t)hb * 0x10001u;
        xkt[b * XKT_B + d * 72 + pos64(h)] = __ushort_as_half(hb);
    }
    for (int i = tid; i < 384; i += THREADS)
        sbias[i] = (i < 128) ? pb0[i] : ((i < 256) ? pb1[i - 128] : pb2[i - 256]);
    __syncthreads();   // fills complete before chunk 0 work

    float C[4][2][2][4];
#pragma unroll
    for (int b = 0; b < 4; ++b)
#pragma unroll
        for (int m = 0; m < 2; ++m)
#pragma unroll
            for (int n = 0; n < 2; ++n)
#pragma unroll
                for (int j = 0; j < 4; ++j) C[b][m][n][j] = 0.f;

    // ldmatrix lane geometry
    const int rowin = (lane & 7) + ((lane >> 3) & 1) * 8;
    const int lrow0 = wy * 32 + rowin;
    const int lcol = ((lane >> 4) & 1) * 16;

    const uint32_t xk_lane = (uint32_t)(gid * 144 + tig * 32);
    const uint32_t xkt_base = sb + OFF_XKT + wx * 4 * 2304;   // batch stride 2304B
    const uint32_t x0_base = sb + OFF_X0 + wx * 4 * 2816;     // batch stride 2816B

    int g = 0, buf = 0;
    for (int L = 0; L < 3; ++L) {
        for (int c = 0; c < 39; ++c, ++g) {
            int nbuf = buf + 1;
            if (nbuf == 3) nbuf = 0;
            if (g + 1 < NCHUNK) {
                uint32_t dst = sb + OFF_W + nbuf * 16384 + tid * 16;
                const __half* src = &WPREP[g + 1][tid * 8];
#pragma unroll
                for (int j = 0; j < 4; ++j) cp16(dst + j * 4096, src + j * 2048);
            }
            cp_commit();

            // pre-barrier loads (layer-stable smem): x0 dups for h = c
            uint32_t x0lo[4], x0hi[4];
#pragma unroll
            for (int bb = 0; bb < 4; ++bb) {
                uint32_t xa = x0_base + (bb * X0_B + gid * 44 + c) * 4;
                x0lo[bb] = lds32(xa);
                x0hi[bb] = lds32(xa + 1408);
            }

            cp_wait<1>();
            __syncthreads();   // W chunk g resident in buf

            const uint32_t wbase = sb + OFF_W + buf * 16384;

            // layer 0 (folded upper triangle): valid k-slabs are [c>>4 .. 2];
            // layers 1/2: [0 .. 3].
            const int klo = (L == 0) ? (c >> 4) : 0;
            const int khi = (L == 0) ? 2 : 3;

            for (int ks = klo; ks <= khi; ++ks) {
                uint32_t A0[4], A1[4];
                ldsm4(A0, wbase + SW128((uint32_t)(lrow0 * 128 + ks * 32 + lcol)));
                ldsm4(A1, wbase + SW128((uint32_t)((lrow0 + 16) * 128 + ks * 32 + lcol)));
                const uint32_t kbyte = (uint32_t)(ks * 8);
#pragma unroll
                for (int bb = 0; bb < 4; ++bb) {
                    uint32_t xb = xkt_base + bb * 2304 + xk_lane + kbyte;
                    uint32_t rx, ry, qx, qy;
                    lds64(rx, ry, xb);
                    lds64(qx, qy, xb + 1152);
                    uint32_t b00 = hmul2(rx, x0lo[bb]);
                    uint32_t b01 = hmul2(ry, x0lo[bb]);
                    uint32_t b10 = hmul2(qx, x0hi[bb]);
                    uint32_t b11 = hmul2(qy, x0hi[bb]);
                    mma16816(C[bb][0][0], A0, b00, b01);
                    mma16816(C[bb][0][1], A0, b10, b11);
                    mma16816(C[bb][1][0], A1, b00, b01);
                    mma16816(C[bb][1][1], A1, b10, b11);
                }
            }
            buf = nbuf;
            // no trailing barrier: triple-buffered W, xkt read-only within layer
        }

        __syncthreads();   // all MMA reads of xkt done before epilogue overwrites

        // ---- layer epilogue ----
#pragma unroll
        for (int bb = 0; bb < 4; ++bb) {
            float* outp = out + (size_t)(bstart + wx * 4 + bb) * 256;
            __half* xkb = xkt + (wx * 4 + bb) * XKT_B;
#pragma unroll
            for (int m = 0; m < 2; ++m) {
                const int s_r = wy * 32 + m * 16 + gid;      // and s_r + 8
                const float b_r = sbias[L * 128 + s_r];
                const float b_r8 = sbias[L * 128 + s_r + 8];
                float vr = 0.f, vr8 = 0.f;
                const int pos = pos64(s_r & 63);
                const int pos8 = pos64((s_r + 8) & 63);
#pragma unroll
                for (int n = 0; n < 2; ++n)
#pragma unroll
                    for (int j = 0; j < 2; ++j) {
                        const int d = 2 * tig + j + n * 8;
                        float z = fmaxf(C[bb][m][n][j] + b_r, 0.f);
                        float z8 = fmaxf(C[bb][m][n][2 + j] + b_r8, 0.f);
                        if (L < 2 && wy < 2) {
                            xkb[d * 72 + pos] = __float2half_rn(z);
                            xkb[d * 72 + pos8] = __float2half_rn(z8);
                        }
                        vr += z;
                        vr8 += z8;
                    }
                vr += __shfl_xor_sync(0xffffffffu, vr, 1);
                vr += __shfl_xor_sync(0xffffffffu, vr, 2);
                vr8 += __shfl_xor_sync(0xffffffffu, vr8, 1);
                vr8 += __shfl_xor_sync(0xffffffffu, vr8, 2);
                if (tig == 0) {
                    if (L == 2) {
                        outp[128 + s_r] = vr;
                        outp[128 + s_r + 8] = vr8;
                    } else if (wy >= 2) {
                        outp[L * 64 + s_r - 64] = vr;
                        outp[L * 64 + s_r - 64 + 8] = vr8;
                    }
                }
            }
#pragma unroll
            for (int m = 0; m < 2; ++m)
#pragma unroll
                for (int n = 0; n < 2; ++n)
#pragma unroll
                    for (int j = 0; j < 4; ++j) C[bb][m][n][j] = 0.f;
        }
        __syncthreads();   // new xkt visible before next layer
    }
}

extern "C" void kernel_launch(void* const* d_in, const int* in_sizes, int n_in,
                              void* d_out, int out_size) {
    const float *inp = nullptr, *w0 = nullptr, *w1 = nullptr, *w2 = nullptr;
    const float *pb0 = nullptr, *pb1 = nullptr, *pb2 = nullptr;
    for (int i = 0; i < n_in; ++i) {
        const float* p = (const float*)d_in[i];
        int s = in_sizes[i];
        if (s == 2048 * 39 * 16) {
            inp = p;
        } else if (s == 39 * 39 * 128) {
            w0 = p;
        } else if (s == 39 * 64 * 128) {
            if (!w1) w1 = p; else w2 = p;
        } else if (s == 128) {
            if (!pb0) pb0 = p; else if (!pb1) pb1 = p; else pb2 = p;
        }
    }
    cudaFuncSetAttribute(cin_hmma, cudaFuncAttributeMaxDynamicSharedMemorySize, SMEM_TOTAL);
    prep_w<<<(NCHUNK * 8192 + 255) / 256, 256>>>(w0, w1, w2);
    cin_hmma<<<256, THREADS, SMEM_TOTAL>>>(inp, pb0, pb1, pb2, (float*)d_out);
}

// round 13
// speedup vs baseline: 8.5125x; 1.0917x over previous
#include <cuda_runtime.h>
#include <cuda_fp16.h>
#include <stdint.h>

// CIN via mma.sync (HMMA): z[(b,d),s] = sum_{h,k} x0*xk*W.
// CTA: 256 threads = 8 warps, 8 batches. warp = (wy: 32 s) x (wx: 4 batches).
// K in 117 chunks (chunk = (layer, h)); layer 0 weights symmetry-folded
// upper-triangle so chunk h runs ks-slabs [h>>4 .. 2]; layers 1/2 run [0..3].
// xkt row stride 136B (34 words = 2 mod 32) -> B lds64 loads are bank-conflict
// free (2 phases each) instead of the 2-way conflicted 144B layout.

#define THREADS 256
#define NCHUNK 117
#define SW128(o) ((o) ^ ((((uint32_t)(o)) >> 3) & 0x70))

// Pre-swizzled f16 W tiles: [chunk][128 s x 64 k] = 16KB each.
__device__ __half WPREP[NCHUNK][8192];

// dynamic smem layout (bytes)
#define OFF_W    0            // 3 x 16384 triple buffer
#define OFF_XKT  49152        // 8 b x 16 d x 68 f16 = 17408  (row stride 136B)
#define OFF_X0   66560        // 8 b x 16 d x 44 u32 (f16x2 dup) = 22528
#define OFF_BIAS 89088        // 384 f32 = 1536
#define SMEM_TOTAL 90624
#define XKT_B 1088            // f16 per batch (16*68)
#define X0_B 704              // u32 per batch (16*44), row stride 176B

// logical k (0..63) -> physical f16 position within a 64-slot row.
// u32 index = t*8 + ks*2 + r  (t=(k>>1)&3, ks=k>>4, r=(k>>3)&1, b=k&1):
// per (row, ks) a lane's {b0,b1} raw pair is one lds64 at byte t*32 + ks*8.
__host__ __device__ __forceinline__ int pos64(int k) {
    return ((k & 6) << 3) | ((k >> 2) & 12) | ((k >> 2) & 2) | (k & 1);
}

__device__ __forceinline__ uint32_t smem_u32(const void* p) {
    uint32_t a;
    asm("{ .reg .u64 t; cvta.to.shared.u64 t, %1; cvt.u32.u64 %0, t; }" : "=r"(a) : "l"(p));
    return a;
}
__device__ __forceinline__ uint32_t hmul2(uint32_t a, uint32_t b) {
    uint32_t r;
    asm("mul.rn.f16x2 %0, %1, %2;" : "=r"(r) : "r"(a), "r"(b));
    return r;
}
__device__ __forceinline__ void lds64(uint32_t& r0, uint32_t& r1, uint32_t addr) {
    asm volatile("ld.shared.v2.b32 {%0,%1}, [%2];" : "=r"(r0), "=r"(r1) : "r"(addr));
}
__device__ __forceinline__ uint32_t lds32(uint32_t addr) {
    uint32_t r;
    asm volatile("ld.shared.b32 %0, [%1];" : "=r"(r) : "r"(addr));
    return r;
}
__device__ __forceinline__ void ldsm4(uint32_t* a, uint32_t addr) {
    asm volatile("ldmatrix.sync.aligned.m8n8.x4.shared.b16 {%0,%1,%2,%3}, [%4];"
                 : "=r"(a[0]), "=r"(a[1]), "=r"(a[2]), "=r"(a[3]) : "r"(addr));
}
__device__ __forceinline__ void mma16816(float* c, const uint32_t* a, uint32_t b0, uint32_t b1) {
    asm volatile(
        "mma.sync.aligned.m16n8k16.row.col.f32.f16.f16.f32 "
        "{%0,%1,%2,%3}, {%4,%5,%6,%7}, {%8,%9}, {%0,%1,%2,%3};"
        : "+f"(c[0]), "+f"(c[1]), "+f"(c[2]), "+f"(c[3])
        : "r"(a[0]), "r"(a[1]), "r"(a[2]), "r"(a[3]), "r"(b0), "r"(b1));
}
__device__ __forceinline__ void cp16(uint32_t dst, const void* src) {
    asm volatile("cp.async.ca.shared.global [%0], [%1], 16;" :: "r"(dst), "l"(src) : "memory");
}
__device__ __forceinline__ void cp_commit() {
    asm volatile("cp.async.commit_group;" ::: "memory");
}
template <int N>
__device__ __forceinline__ void cp_wait() {
    asm volatile("cp.async.wait_group %0;" :: "n"(N) : "memory");
}

// ---------------------------------------------------------------------------
// prep: W fp32 [h][k][s] -> per-chunk pre-swizzled f16 smem images.
// Layer 0 symmetry-folded: Wf[h][k] = W[h][k]+W[k][h] (k>h), W[h][h], else 0.
// ---------------------------------------------------------------------------
__global__ void __launch_bounds__(256) prep_w(const float* __restrict__ w0,
                                              const float* __restrict__ w1,
                                              const float* __restrict__ w2) {
    int idx = blockIdx.x * 256 + threadIdx.x;
    if (idx >= NCHUNK * 8192) return;
    int g = idx >> 13;
    int i = idx & 8191;
    int L = g / 39, h = g % 39;
    uint32_t o = SW128((uint32_t)(i * 2));   // involution
    int s = o >> 7;
    int k = (o & 127) >> 1;
    float v = 0.f;
    if (L == 0) {
        if (k < 39 && k >= h) {
            v = w0[(h * 39 + k) * 128 + s];
            if (k > h) v += w0[(k * 39 + h) * 128 + s];
        }
    } else if (L == 1) {
        v = w1[(h * 64 + k) * 128 + s];
    } else {
        v = w2[(h * 64 + k) * 128 + s];
    }
    WPREP[g][i] = __float2half_rn(v);
}

// ---------------------------------------------------------------------------
// main fused kernel
// ---------------------------------------------------------------------------
__global__ void __launch_bounds__(THREADS, 2)
cin_hmma(const float* __restrict__ inputs,
         const float* __restrict__ pb0, const float* __restrict__ pb1,
         const float* __restrict__ pb2, float* __restrict__ out) {
    extern __shared__ char smem[];
    const uint32_t sb = smem_u32(smem);
    const int tid = threadIdx.x;
    const int lane = tid & 31;
    const int wid = tid >> 5;
    const int wy = wid >> 1;          // s-group: s in [wy*32, wy*32+32)
    const int wx = wid & 1;           // batch-group: local batches wx*4..wx*4+3
    const int gid = lane >> 2;        // 0..7  (d row / B n index)
    const int tig = lane & 3;         // 0..3
    const int bstart = blockIdx.x * 8;

    __half* xkt = (__half*)(smem + OFF_XKT);
    uint32_t* x0d = (uint32_t*)(smem + OFF_X0);
    float* sbias = (float*)(smem + OFF_BIAS);

    // prefetch chunk 0 into buf 0
    {
        uint32_t dst = sb + OFF_W + tid * 16;
        const __half* src = &WPREP[0][tid * 8];
#pragma unroll
        for (int j = 0; j < 4; ++j) cp16(dst + j * 4096, src + j * 2048);
        cp_commit();
    }

    // zero xkt (covers layer-0 k pad + stride pad), then fill
    for (int i = tid; i < 4352; i += THREADS) ((uint32_t*)xkt)[i] = 0u;
    __syncthreads();
    for (int i = tid; i < 8 * 624; i += THREADS) {
        int b = i / 624, r = i % 624, h = r / 16, d = r % 16;
        float v = inputs[(size_t)(bstart + b) * 624 + r];
        uint16_t hb = __half_as_ushort(__float2half_rn(v));
        x0d[b * X0_B + d * 44 + h] = (uint32_t)hb * 0x10001u;
        xkt[b * XKT_B + d * 68 + pos64(h)] = __ushort_as_half(hb);
    }
    for (int i = tid; i < 384; i += THREADS)
        sbias[i] = (i < 128) ? pb0[i] : ((i < 256) ? pb1[i - 128] : pb2[i - 256]);
    __syncthreads();   // fills complete before chunk 0 work

    float C[4][2][2][4];
#pragma unroll
    for (int b = 0; b < 4; ++b)
#pragma unroll
        for (int m = 0; m < 2; ++m)
#pragma unroll
            for (int n = 0; n < 2; ++n)
#pragma unroll
                for (int j = 0; j < 4; ++j) C[b][m][n][j] = 0.f;

    // ldmatrix lane geometry
    const int rowin = (lane & 7) + ((lane >> 3) & 1) * 8;
    const int lrow0 = wy * 32 + rowin;
    const int lcol = ((lane >> 4) & 1) * 16;

    // B lane address: bank word = (2*gid + 8*tig) mod 32 -> conflict-free halves
    const uint32_t xk_lane = (uint32_t)(gid * 136 + tig * 32);
    const uint32_t xkt_base = sb + OFF_XKT + wx * 4 * 2176;   // batch stride 2176B
    const uint32_t x0_base = sb + OFF_X0 + wx * 4 * 2816;     // batch stride 2816B

    int g = 0, buf = 0;
    for (int L = 0; L < 3; ++L) {
        for (int c = 0; c < 39; ++c, ++g) {
            int nbuf = buf + 1;
            if (nbuf == 3) nbuf = 0;
            if (g + 1 < NCHUNK) {
                uint32_t dst = sb + OFF_W + nbuf * 16384 + tid * 16;
                const __half* src = &WPREP[g + 1][tid * 8];
#pragma unroll
                for (int j = 0; j < 4; ++j) cp16(dst + j * 4096, src + j * 2048);
            }
            cp_commit();

            // pre-barrier loads (layer-stable smem): x0 dups for h = c
            uint32_t x0lo[4], x0hi[4];
#pragma unroll
            for (int bb = 0; bb < 4; ++bb) {
                uint32_t xa = x0_base + (bb * X0_B + gid * 44 + c) * 4;
                x0lo[bb] = lds32(xa);
                x0hi[bb] = lds32(xa + 1408);
            }

            cp_wait<1>();
            __syncthreads();   // W chunk g resident in buf

            const uint32_t wbase = sb + OFF_W + buf * 16384;

            // layer 0 (folded upper triangle): valid k-slabs [c>>4 .. 2];
            // layers 1/2: [0 .. 3].
            const int klo = (L == 0) ? (c >> 4) : 0;
            const int khi = (L == 0) ? 2 : 3;

            for (int ks = klo; ks <= khi; ++ks) {
                uint32_t A0[4], A1[4];
                ldsm4(A0, wbase + SW128((uint32_t)(lrow0 * 128 + ks * 32 + lcol)));
                ldsm4(A1, wbase + SW128((uint32_t)((lrow0 + 16) * 128 + ks * 32 + lcol)));
                const uint32_t kbyte = (uint32_t)(ks * 8);
#pragma unroll
                for (int bb = 0; bb < 4; ++bb) {
                    uint32_t xb = xkt_base + bb * 2176 + xk_lane + kbyte;
                    uint32_t rx, ry, qx, qy;
                    lds64(rx, ry, xb);
                    lds64(qx, qy, xb + 1088);
                    uint32_t b00 = hmul2(rx, x0lo[bb]);
                    uint32_t b01 = hmul2(ry, x0lo[bb]);
                    uint32_t b10 = hmul2(qx, x0hi[bb]);
                    uint32_t b11 = hmul2(qy, x0hi[bb]);
                    mma16816(C[bb][0][0], A0, b00, b01);
                    mma16816(C[bb][0][1], A0, b10, b11);
                    mma16816(C[bb][1][0], A1, b00, b01);
                    mma16816(C[bb][1][1], A1, b10, b11);
                }
            }
            buf = nbuf;
            // no trailing barrier: triple-buffered W, xkt read-only within layer
        }

        __syncthreads();   // all MMA reads of xkt done before epilogue overwrites

        // ---- layer epilogue ----
#pragma unroll
        for (int bb = 0; bb < 4; ++bb) {
            float* outp = out + (size_t)(bstart + wx * 4 + bb) * 256;
            __half* xkb = xkt + (wx * 4 + bb) * XKT_B;
#pragma unroll
            for (int m = 0; m < 2; ++m) {
                const int s_r = wy * 32 + m * 16 + gid;      // and s_r + 8
                const float b_r = sbias[L * 128 + s_r];
                const float b_r8 = sbias[L * 128 + s_r + 8];
                float vr = 0.f, vr8 = 0.f;
                const int pos = pos64(s_r & 63);
                const int pos8 = pos64((s_r + 8) & 63);
#pragma unroll
                for (int n = 0; n < 2; ++n)
#pragma unroll
                    for (int j = 0; j < 2; ++j) {
                        const int d = 2 * tig + j + n * 8;
                        float z = fmaxf(C[bb][m][n][j] + b_r, 0.f);
                        float z8 = fmaxf(C[bb][m][n][2 + j] + b_r8, 0.f);
                        if (L < 2 && wy < 2) {
                            xkb[d * 68 + pos] = __float2half_rn(z);
                            xkb[d * 68 + pos8] = __float2half_rn(z8);
                        }
                        vr += z;
                        vr8 += z8;
                    }
                vr += __shfl_xor_sync(0xffffffffu, vr, 1);
                vr += __shfl_xor_sync(0xffffffffu, vr, 2);
                vr8 += __shfl_xor_sync(0xffffffffu, vr8, 1);
                vr8 += __shfl_xor_sync(0xffffffffu, vr8, 2);
                if (tig == 0) {
                    if (L == 2) {
                        outp[128 + s_r] = vr;
                        outp[128 + s_r + 8] = vr8;
                    } else if (wy >= 2) {
                        outp[L * 64 + s_r - 64] = vr;
                        outp[L * 64 + s_r - 64 + 8] = vr8;
                    }
                }
            }
#pragma unroll
            for (int m = 0; m < 2; ++m)
#pragma unroll
                for (int n = 0; n < 2; ++n)
#pragma unroll
                    for (int j = 0; j < 4; ++j) C[bb][m][n][j] = 0.f;
        }
        __syncthreads();   // new xkt visible before next layer
    }
}

extern "C" void kernel_launch(void* const* d_in, const int* in_sizes, int n_in,
                              void* d_out, int out_size) {
    const float *inp = nullptr, *w0 = nullptr, *w1 = nullptr, *w2 = nullptr;
    const float *pb0 = nullptr, *pb1 = nullptr, *pb2 = nullptr;
    for (int i = 0; i < n_in; ++i) {
        const float* p = (const float*)d_in[i];
        int s = in_sizes[i];
        if (s == 2048 * 39 * 16) {
            inp = p;
        } else if (s == 39 * 39 * 128) {
            w0 = p;
        } else if (s == 39 * 64 * 128) {
            if (!w1) w1 = p; else w2 = p;
        } else if (s == 128) {
            if (!pb0) pb0 = p; else if (!pb1) pb1 = p; else pb2 = p;
        }
    }
    cudaFuncSetAttribute(cin_hmma, cudaFuncAttributeMaxDynamicSharedMemorySize, SMEM_TOTAL);
    prep_w<<<(NCHUNK * 8192 + 255) / 256, 256>>>(w0, w1, w2);
    cin_hmma<<<256, THREADS, SMEM_TOTAL>>>(inp, pb0, pb1, pb2, (float*)d_out);
}